// round 15
// baseline (speedup 1.0000x reference)
#include <cuda_runtime.h>
#include <cuda_bf16.h>
#include <cstdint>
#include <cstddef>

#define BB 8
#define TT 2048      // S_dec
#define EE 2048      // S_enc
#define DDIM 1024    // D

// ---------------- scratch (static device arrays; no allocation) ------------
__device__ float g_scores[(size_t)BB * TT * EE];                 // [b][t][e] fp32
__device__ __nv_bfloat16 g_encH[(size_t)BB * EE * DDIM];
__device__ __nv_bfloat16 g_encL[(size_t)BB * EE * DDIM];
__device__ __nv_bfloat16 g_decH[(size_t)BB * TT * DDIM];
__device__ __nv_bfloat16 g_decL[(size_t)BB * TT * DDIM];
__device__ __nv_bfloat16 g_encTH[(size_t)BB * DDIM * EE];        // [b][d][e]
__device__ __nv_bfloat16 g_encTL[(size_t)BB * DDIM * EE];
__device__ __nv_bfloat16 g_ptH[(size_t)BB * TT * EE];            // P^T [b][t][e]
__device__ __nv_bfloat16 g_ptL[(size_t)BB * TT * EE];
#define NSEG 32                                                   // TT/128 * 2 warp-rows
__device__ float g_mpart[NSEG * BB * EE];
__device__ float g_spart[NSEG * BB * EE];
__device__ float g_colM[BB * EE];
__device__ float g_colIS[BB * EE];

// ---------------- helpers ---------------------------------------------------
__device__ __forceinline__ uint32_t smem_u32(const void* p) {
    uint32_t a;
    asm("{ .reg .u64 t; cvta.to.shared.u64 t, %1; cvt.u32.u64 %0, t; }"
        : "=r"(a) : "l"(p));
    return a;
}
__device__ __forceinline__ void cp_async16(uint32_t s, const void* g) {
    asm volatile("cp.async.cg.shared.global [%0], [%1], 16;" :: "r"(s), "l"(g) : "memory");
}
__device__ __forceinline__ void cp_commit() {
    asm volatile("cp.async.commit_group;" ::: "memory");
}
__device__ __forceinline__ void cp_wait1() { asm volatile("cp.async.wait_group 1;" ::: "memory"); }
__device__ __forceinline__ void cp_wait0() { asm volatile("cp.async.wait_group 0;" ::: "memory"); }

__device__ __forceinline__ void ldsm_x4(uint32_t& r0, uint32_t& r1, uint32_t& r2, uint32_t& r3,
                                        uint32_t addr) {
    asm volatile("ldmatrix.sync.aligned.m8n8.x4.shared.b16 {%0,%1,%2,%3}, [%4];"
        : "=r"(r0), "=r"(r1), "=r"(r2), "=r"(r3) : "r"(addr));
}
__device__ __forceinline__ void mma16816(float& d0, float& d1, float& d2, float& d3,
                                         uint32_t a0, uint32_t a1, uint32_t a2, uint32_t a3,
                                         uint32_t b0, uint32_t b1) {
    asm volatile("mma.sync.aligned.m16n8k16.row.col.f32.bf16.bf16.f32 "
                 "{%0,%1,%2,%3}, {%4,%5,%6,%7}, {%8,%9}, {%0,%1,%2,%3};"
                 : "+f"(d0), "+f"(d1), "+f"(d2), "+f"(d3)
                 : "r"(a0), "r"(a1), "r"(a2), "r"(a3), "r"(b0), "r"(b1));
}

#define SW128(o) ((o) ^ (((o) >> 3) & 0x70))
// CTA tile: 128 (M) x 256 (N), BK = 64 bf16 (128B rows, SW128)
#define A_TILE_BYTES 16384                 // 128 rows x 128B
#define B_TILE_BYTES 32768                 // 256 rows x 128B
#define STAGE_BYTES (2 * A_TILE_BYTES + 2 * B_TILE_BYTES)   // Ah, Al, Bh, Bl = 96KB
#define NSTAGE 2
#define GEMM_SMEM (1024 + NSTAGE * STAGE_BYTES)             // ~193KB

// load one 64-K-wide stage
__device__ __forceinline__ void load_stage(uint32_t db, int stage,
    const __nv_bfloat16* pAh, const __nv_bfloat16* pAl,
    const __nv_bfloat16* pBh, const __nv_bfloat16* pBl,
    int k0, int K, int tid)
{
    uint32_t sbase = db + stage * STAGE_BYTES;
    // A tiles: 128 rows x 8 cols(16B) = 1024 cp per tile
    {
        const __nv_bfloat16* sa[2] = { pAh + k0, pAl + k0 };
        #pragma unroll
        for (int tt = 0; tt < 2; tt++) {
            uint32_t tb = sbase + tt * A_TILE_BYTES;
            #pragma unroll
            for (int ii = 0; ii < 4; ii++) {
                int i = tid + ii * 256;
                int r = i >> 3, c = i & 7;
                cp_async16(tb + SW128(r * 128 + c * 16), sa[tt] + (size_t)r * K + c * 8);
            }
        }
    }
    // B tiles: 256 rows x 8 cols(16B) = 2048 cp per tile
    {
        const __nv_bfloat16* sb[2] = { pBh + k0, pBl + k0 };
        #pragma unroll
        for (int tt = 0; tt < 2; tt++) {
            uint32_t tb = sbase + 2 * A_TILE_BYTES + tt * B_TILE_BYTES;
            #pragma unroll
            for (int ii = 0; ii < 8; ii++) {
                int i = tid + ii * 256;
                int r = i >> 3, c = i & 7;
                cp_async16(tb + SW128(r * 128 + c * 16), sb[tt] + (size_t)r * K + c * 8);
            }
        }
    }
    cp_commit();
}

// ---------------- GEMM: C[M,N] = 3-term-split A[M,K] * B[N,K]^T -------------
// which==0 additionally emits per-column (over this CTA's 128 rows, split per
// warp-row half) softmax partials: max and sum-exp -> g_mpart/g_spart.
__global__ __launch_bounds__(256, 1)
void gemm_bf16x3(float* __restrict__ outPtr, int which)
{
    const __nv_bfloat16 *aH, *aL, *bH, *bL;
    float* C;
    int M, N, K;
    if (which == 0) {  // scores^T: C[t][e] = sum_d dec[t,d] * enc[e,d]
        aH = g_decH; aL = g_decL; bH = g_encH; bL = g_encL;
        C = g_scores; M = TT; N = EE; K = DDIM;
    } else {           // out[t][d] = sum_e Pt[t,e] * encT[d,e]
        aH = g_ptH; aL = g_ptL; bH = g_encTH; bL = g_encTL;
        C = outPtr; M = TT; N = DDIM; K = EE;
    }

    extern __shared__ char dsm[];
    const uint32_t db = (smem_u32(dsm) + 1023u) & ~1023u;

    const int tid  = threadIdx.x;
    const int wid  = tid >> 5;
    const int lane = tid & 31;
    const int b    = blockIdx.z;
    const int nc0  = blockIdx.x * 256;
    const int mr0  = blockIdx.y * 128;

    const int wm = wid & 1;          // 2 warps in M (64 rows each)
    const int wn = wid >> 1;         // 4 warps in N (64 cols each)
    const int wmr = wm * 64;
    const int wnr = wn * 64;

    // ldmatrix lane addressing: sub = lane>>3
    const int sub = lane >> 3;
    const int lr  = ((sub & 1) << 3) + (lane & 7);  // row within 16-row block
    const int lc  = sub >> 1;                        // kchunk (16B) within k16

    const __nv_bfloat16* pAh = aH + (size_t)b * M * K + (size_t)mr0 * K;
    const __nv_bfloat16* pAl = aL + (size_t)b * M * K + (size_t)mr0 * K;
    const __nv_bfloat16* pBh = bH + (size_t)b * N * K + (size_t)nc0 * K;
    const __nv_bfloat16* pBl = bL + (size_t)b * N * K + (size_t)nc0 * K;

    float acc[4][8][4];
    #pragma unroll
    for (int i = 0; i < 4; i++)
        #pragma unroll
        for (int j = 0; j < 8; j++) {
            acc[i][j][0] = 0.f; acc[i][j][1] = 0.f;
            acc[i][j][2] = 0.f; acc[i][j][3] = 0.f;
        }

    const int NC = K / 64;
    load_stage(db, 0, pAh, pAl, pBh, pBl, 0, K, tid);
    load_stage(db, 1, pAh, pAl, pBh, pBl, 64, K, tid);

    for (int c = 0; c < NC; c++) {
        if (c + 1 < NC) cp_wait1(); else cp_wait0();
        __syncthreads();   // stage c resident

        const uint32_t sb  = db + (c & 1) * STAGE_BYTES;
        const uint32_t tAh = sb;
        const uint32_t tAl = sb + A_TILE_BYTES;
        const uint32_t tBh = sb + 2 * A_TILE_BYTES;
        const uint32_t tBl = sb + 2 * A_TILE_BYTES + B_TILE_BYTES;

        #pragma unroll
        for (int kk = 0; kk < 4; kk++) {
            const int c16 = (2 * kk + lc) * 16;
            uint32_t ah[4][4], al[4][4], bh[4][4], bl[4][4];
            #pragma unroll
            for (int mi = 0; mi < 4; mi++) {
                const uint32_t off = SW128((uint32_t)(wmr + mi * 16 + lr) * 128 + c16);
                ldsm_x4(ah[mi][0], ah[mi][1], ah[mi][2], ah[mi][3], tAh + off);
                ldsm_x4(al[mi][0], al[mi][1], al[mi][2], al[mi][3], tAl + off);
            }
            #pragma unroll
            for (int nb = 0; nb < 4; nb++) {
                const uint32_t off = SW128((uint32_t)(wnr + nb * 16 + lr) * 128 + c16);
                ldsm_x4(bh[nb][0], bh[nb][1], bh[nb][2], bh[nb][3], tBh + off);
                ldsm_x4(bl[nb][0], bl[nb][1], bl[nb][2], bl[nb][3], tBl + off);
            }
            // ldmatrix.x4 matrix order (our addressing):
            //   reg0 = n0-7|k0-7, reg1 = n8-15|k0-7, reg2 = n0-7|k8-15, reg3 = n8-15|k8-15
            // mma B fragment wants {k-lo, k-hi} of ONE n-block:
            //   n-block even -> (reg0, reg2); n-block odd -> (reg1, reg3)
            #pragma unroll
            for (int mi = 0; mi < 4; mi++)
                #pragma unroll
                for (int ni = 0; ni < 8; ni++) {
                    const int nb = ni >> 1, sel = ni & 1;
                    float* d = acc[mi][ni];
                    mma16816(d[0], d[1], d[2], d[3],
                             ah[mi][0], ah[mi][1], ah[mi][2], ah[mi][3],
                             bh[nb][sel], bh[nb][sel + 2]);
                    mma16816(d[0], d[1], d[2], d[3],
                             ah[mi][0], ah[mi][1], ah[mi][2], ah[mi][3],
                             bl[nb][sel], bl[nb][sel + 2]);
                    mma16816(d[0], d[1], d[2], d[3],
                             al[mi][0], al[mi][1], al[mi][2], al[mi][3],
                             bh[nb][sel], bh[nb][sel + 2]);
                }
        }

        __syncthreads();   // all warps done reading stage c
        if (c + 2 < NC)
            load_stage(db, c & 1, pAh, pAl, pBh, pBl, (c + 2) * 64, K, tid);
    }

    // epilogue: C fragment: d0,d1 -> (row g, col 2*tg), d2,d3 -> (row g+8, col 2*tg)
    const int g  = lane >> 2;
    const int tg = lane & 3;
    float* Cb = C + (size_t)b * M * N;
    #pragma unroll
    for (int mi = 0; mi < 4; mi++) {
        const int r0 = mr0 + wmr + mi * 16 + g;
        #pragma unroll
        for (int ni = 0; ni < 8; ni++) {
            const int col = nc0 + wnr + ni * 8 + 2 * tg;
            float2 v0 = make_float2(acc[mi][ni][0], acc[mi][ni][1]);
            float2 v1 = make_float2(acc[mi][ni][2], acc[mi][ni][3]);
            *(float2*)&Cb[(size_t)r0 * N + col]       = v0;
            *(float2*)&Cb[(size_t)(r0 + 8) * N + col] = v1;
        }
    }

    // fused column softmax partials over this warp's 64 rows (scores GEMM only)
    if (which == 0) {
        const int seg = blockIdx.y * 2 + wm;               // 0..31
        float* mp = g_mpart + ((size_t)b * NSEG + seg) * EE;
        float* sp = g_spart + ((size_t)b * NSEG + seg) * EE;
        #pragma unroll
        for (int ni = 0; ni < 8; ni++) {
            float m0 = -1e30f, m1 = -1e30f;
            #pragma unroll
            for (int mi = 0; mi < 4; mi++) {
                m0 = fmaxf(m0, fmaxf(acc[mi][ni][0], acc[mi][ni][2]));
                m1 = fmaxf(m1, fmaxf(acc[mi][ni][1], acc[mi][ni][3]));
            }
            #pragma unroll
            for (int o = 4; o < 32; o <<= 1) {
                m0 = fmaxf(m0, __shfl_xor_sync(0xffffffffu, m0, o));
                m1 = fmaxf(m1, __shfl_xor_sync(0xffffffffu, m1, o));
            }
            float s0 = 0.f, s1 = 0.f;
            #pragma unroll
            for (int mi = 0; mi < 4; mi++) {
                s0 += __expf(acc[mi][ni][0] - m0) + __expf(acc[mi][ni][2] - m0);
                s1 += __expf(acc[mi][ni][1] - m1) + __expf(acc[mi][ni][3] - m1);
            }
            #pragma unroll
            for (int o = 4; o < 32; o <<= 1) {
                s0 += __shfl_xor_sync(0xffffffffu, s0, o);
                s1 += __shfl_xor_sync(0xffffffffu, s1, o);
            }
            if (lane < 4) {   // g==0 lanes; tg == lane
                const int e = nc0 + wnr + ni * 8 + 2 * lane;
                mp[e] = m0; mp[e + 1] = m1;
                sp[e] = s0; sp[e + 1] = s1;
            }
        }
    }
}

// ---------------- split fp32 -> (hi, lo) bf16 -------------------------------
__device__ __forceinline__ void split1(float x, __nv_bfloat16& h, __nv_bfloat16& l) {
    h = __float2bfloat16(x);
    l = __float2bfloat16(x - __bfloat162float(h));
}

// dec: row-major split only
__global__ __launch_bounds__(256)
void split_dec(const float* __restrict__ dec)
{
    size_t j = (size_t)blockIdx.x * blockDim.x + threadIdx.x;   // over 4.19M float4
    float4 v = ((const float4*)dec)[j];
    __nv_bfloat16 h0, h1, h2, h3, l0, l1, l2, l3;
    split1(v.x, h0, l0); split1(v.y, h1, l1); split1(v.z, h2, l2); split1(v.w, h3, l3);
    *(__nv_bfloat162*)&g_decH[j * 4]     = make_bfloat162(h0, h1);
    *(__nv_bfloat162*)&g_decH[j * 4 + 2] = make_bfloat162(h2, h3);
    *(__nv_bfloat162*)&g_decL[j * 4]     = make_bfloat162(l0, l1);
    *(__nv_bfloat162*)&g_decL[j * 4 + 2] = make_bfloat162(l2, l3);
}

// enc: single read -> row-major split (encH/encL) + transposed split (encTH/encTL)
__global__ __launch_bounds__(256)
void split_enc_fused(const float* __restrict__ enc)
{
    __shared__ float ts[32][33];
    const int b = blockIdx.z;
    const int d0 = blockIdx.x * 32;
    const int e0 = blockIdx.y * 32;
    const int tx = threadIdx.x, ty = threadIdx.y;   // (32, 8)
    const float* src = enc + (size_t)b * EE * DDIM;
    __nv_bfloat16* rh = g_encH + (size_t)b * EE * DDIM;
    __nv_bfloat16* rl = g_encL + (size_t)b * EE * DDIM;
    #pragma unroll
    for (int j = 0; j < 4; j++) {
        const size_t o = (size_t)(e0 + ty + 8 * j) * DDIM + d0 + tx;
        float v = src[o];
        ts[ty + 8 * j][tx] = v;
        __nv_bfloat16 h, l; split1(v, h, l);
        rh[o] = h; rl[o] = l;
    }
    __syncthreads();
    __nv_bfloat16* oh = g_encTH + (size_t)b * DDIM * EE;
    __nv_bfloat16* ol = g_encTL + (size_t)b * DDIM * EE;
    #pragma unroll
    for (int j = 0; j < 4; j++) {
        float v = ts[tx][ty + 8 * j];
        __nv_bfloat16 h, l; split1(v, h, l);
        size_t o = (size_t)(d0 + ty + 8 * j) * EE + e0 + tx;
        oh[o] = h; ol[o] = l;
    }
}

// ---------------- combine 32 segments -> column max & inv-sum ---------------
__global__ __launch_bounds__(256)
void colstats_comb()
{
    const int i = blockIdx.x * 256 + threadIdx.x;   // over BB*EE
    const int b = i / EE, e = i % EE;
    float M = -1e30f;
    #pragma unroll
    for (int s = 0; s < NSEG; s++)
        M = fmaxf(M, g_mpart[((size_t)b * NSEG + s) * EE + e]);
    float S = 0.f;
    #pragma unroll
    for (int s = 0; s < NSEG; s++) {
        size_t idx = ((size_t)b * NSEG + s) * EE + e;
        S += g_spart[idx] * __expf(g_mpart[idx] - M);
    }
    g_colM[i] = M;
    g_colIS[i] = 1.0f / S;
}

// ---------------- normalize + split: scores -> PtH/PtL ----------------------
__global__ __launch_bounds__(256)
void softmax_split()
{
    size_t i = ((size_t)blockIdx.x * blockDim.x + threadIdx.x) * 4;  // [b][t][e]
    const int e = (int)(i % EE);
    const int b = (int)(i / ((size_t)TT * EE));
    float4 v = *(const float4*)&g_scores[i];
    float4 m4 = *(const float4*)&g_colM[b * EE + e];
    float4 s4 = *(const float4*)&g_colIS[b * EE + e];
    float p0 = __expf(v.x - m4.x) * s4.x;
    float p1 = __expf(v.y - m4.y) * s4.y;
    float p2 = __expf(v.z - m4.z) * s4.z;
    float p3 = __expf(v.w - m4.w) * s4.w;
    __nv_bfloat16 h0, h1, h2, h3, l0, l1, l2, l3;
    split1(p0, h0, l0); split1(p1, h1, l1); split1(p2, h2, l2); split1(p3, h3, l3);
    *(__nv_bfloat162*)&g_ptH[i]     = make_bfloat162(h0, h1);
    *(__nv_bfloat162*)&g_ptH[i + 2] = make_bfloat162(h2, h3);
    *(__nv_bfloat162*)&g_ptL[i]     = make_bfloat162(l0, l1);
    *(__nv_bfloat162*)&g_ptL[i + 2] = make_bfloat162(l2, l3);
}

// ---------------------------------------------------------------------------
extern "C" void kernel_launch(void* const* d_in, const int* in_sizes, int n_in,
                              void* d_out, int out_size)
{
    const float* enc = (const float*)d_in[0];
    const float* dec = (const float*)d_in[1];
    float* out = (float*)d_out;

    cudaFuncSetAttribute(gemm_bf16x3, cudaFuncAttributeMaxDynamicSharedMemorySize,
                         GEMM_SMEM);

    {
        dim3 g(DDIM / 32, EE / 32, BB);
        split_enc_fused<<<g, dim3(32, 8)>>>(enc);
    }
    split_dec<<<16384, 256>>>(dec);
    {
        dim3 g(EE / 256, TT / 128, BB);
        gemm_bf16x3<<<g, 256, GEMM_SMEM>>>(out, 0);
    }
    colstats_comb<<<BB * EE / 256, 256>>>();
    softmax_split<<<32768, 256>>>();
    {
        dim3 g(DDIM / 256, TT / 128, BB);
        gemm_bf16x3<<<g, 256, GEMM_SMEM>>>(out, 1);
    }
}

// round 17
// speedup vs baseline: 1.4661x; 1.4661x over previous
#include <cuda_runtime.h>
#include <cuda_bf16.h>
#include <cuda_fp16.h>
#include <cstdint>
#include <cstddef>

#define BB 8
#define TT 2048      // S_dec
#define EE 2048      // S_enc
#define DDIM 1024    // D

// ---------------- scratch (static device arrays; no allocation) ------------
__device__ float g_scores[(size_t)BB * TT * EE];                 // [b][t][e] fp32
__device__ __nv_bfloat16 g_encH[(size_t)BB * EE * DDIM];
__device__ __nv_bfloat16 g_encL[(size_t)BB * EE * DDIM];
__device__ __nv_bfloat16 g_decH[(size_t)BB * TT * DDIM];
__device__ __nv_bfloat16 g_decL[(size_t)BB * TT * DDIM];
__device__ __half g_encTF[(size_t)BB * DDIM * EE];               // [b][d][e] fp16
__device__ __half g_ptF[(size_t)BB * TT * EE];                   // P^T [b][t][e] fp16
#define NSEG 32                                                   // TT/128 * 2 warp-rows
__device__ float g_mpart[NSEG * BB * EE];
__device__ float g_spart[NSEG * BB * EE];
__device__ float g_colM[BB * EE];
__device__ float g_colIS[BB * EE];

// ---------------- helpers ---------------------------------------------------
__device__ __forceinline__ uint32_t smem_u32(const void* p) {
    uint32_t a;
    asm("{ .reg .u64 t; cvta.to.shared.u64 t, %1; cvt.u32.u64 %0, t; }"
        : "=r"(a) : "l"(p));
    return a;
}
__device__ __forceinline__ void cp_async16(uint32_t s, const void* g) {
    asm volatile("cp.async.cg.shared.global [%0], [%1], 16;" :: "r"(s), "l"(g) : "memory");
}
__device__ __forceinline__ void cp_commit() {
    asm volatile("cp.async.commit_group;" ::: "memory");
}
__device__ __forceinline__ void cp_wait1() { asm volatile("cp.async.wait_group 1;" ::: "memory"); }
__device__ __forceinline__ void cp_wait0() { asm volatile("cp.async.wait_group 0;" ::: "memory"); }

__device__ __forceinline__ void ldsm_x4(uint32_t& r0, uint32_t& r1, uint32_t& r2, uint32_t& r3,
                                        uint32_t addr) {
    asm volatile("ldmatrix.sync.aligned.m8n8.x4.shared.b16 {%0,%1,%2,%3}, [%4];"
        : "=r"(r0), "=r"(r1), "=r"(r2), "=r"(r3) : "r"(addr));
}
__device__ __forceinline__ void mma16816(float& d0, float& d1, float& d2, float& d3,
                                         uint32_t a0, uint32_t a1, uint32_t a2, uint32_t a3,
                                         uint32_t b0, uint32_t b1) {
    asm volatile("mma.sync.aligned.m16n8k16.row.col.f32.bf16.bf16.f32 "
                 "{%0,%1,%2,%3}, {%4,%5,%6,%7}, {%8,%9}, {%0,%1,%2,%3};"
                 : "+f"(d0), "+f"(d1), "+f"(d2), "+f"(d3)
                 : "r"(a0), "r"(a1), "r"(a2), "r"(a3), "r"(b0), "r"(b1));
}
__device__ __forceinline__ void mma16816h(float& d0, float& d1, float& d2, float& d3,
                                          uint32_t a0, uint32_t a1, uint32_t a2, uint32_t a3,
                                          uint32_t b0, uint32_t b1) {
    asm volatile("mma.sync.aligned.m16n8k16.row.col.f32.f16.f16.f32 "
                 "{%0,%1,%2,%3}, {%4,%5,%6,%7}, {%8,%9}, {%0,%1,%2,%3};"
                 : "+f"(d0), "+f"(d1), "+f"(d2), "+f"(d3)
                 : "r"(a0), "r"(a1), "r"(a2), "r"(a3), "r"(b0), "r"(b1));
}

#define SW128(o) ((o) ^ (((o) >> 3) & 0x70))
#define TILE_BYTES 16384                   // 128 rows x 128B (64 elems of 2B)
#define STAGE_BYTES (4 * TILE_BYTES)       // GEMM1: Ah, Al, Bh, Bl
#define NSTAGE 3
#define GEMM_SMEM (1024 + NSTAGE * STAGE_BYTES)
#define G2_STAGE_BYTES (2 * TILE_BYTES)    // GEMM2: A, B
#define G2_SMEM (1024 + NSTAGE * G2_STAGE_BYTES)

// register fragment set for one k16 step (GEMM1)
struct Frag {
    uint32_t ah[4][4];
    uint32_t al[4][4];
    uint32_t bh[2][4];
    uint32_t bl[2][4];
};

// GEMM1: load one 64-K-wide stage: 4 operand tiles of 128 rows x 64 bf16
__device__ __forceinline__ void load_stage(uint32_t db, int stage,
    const __nv_bfloat16* pAh, const __nv_bfloat16* pAl,
    const __nv_bfloat16* pBh, const __nv_bfloat16* pBl,
    int k0, int K, int tid)
{
    const __nv_bfloat16* srcs[4] = { pAh + k0, pAl + k0, pBh + k0, pBl + k0 };
    uint32_t sbase = db + stage * STAGE_BYTES;
    #pragma unroll
    for (int tt = 0; tt < 4; tt++) {
        const __nv_bfloat16* s = srcs[tt];
        uint32_t tb = sbase + tt * TILE_BYTES;
        #pragma unroll
        for (int ii = 0; ii < 4; ii++) {
            int i = tid + ii * 256;
            int r = i >> 3, c = i & 7;
            cp_async16(tb + SW128(r * 128 + c * 16), s + (size_t)r * K + c * 8);
        }
    }
    cp_commit();
}

__device__ __forceinline__ void load_frags(Frag& f,
    uint32_t tAh, uint32_t tAl, uint32_t tBh, uint32_t tBl,
    int kk, int lc, int lr, int wmr, int wnr)
{
    const int c16 = (2 * kk + lc) * 16;
    #pragma unroll
    for (int mi = 0; mi < 4; mi++) {
        const uint32_t off = SW128((uint32_t)(wmr + mi * 16 + lr) * 128 + c16);
        ldsm_x4(f.ah[mi][0], f.ah[mi][1], f.ah[mi][2], f.ah[mi][3], tAh + off);
        ldsm_x4(f.al[mi][0], f.al[mi][1], f.al[mi][2], f.al[mi][3], tAl + off);
    }
    #pragma unroll
    for (int nb = 0; nb < 2; nb++) {
        const uint32_t off = SW128((uint32_t)(wnr + nb * 16 + lr) * 128 + c16);
        ldsm_x4(f.bh[nb][0], f.bh[nb][1], f.bh[nb][2], f.bh[nb][3], tBh + off);
        ldsm_x4(f.bl[nb][0], f.bl[nb][1], f.bl[nb][2], f.bl[nb][3], tBl + off);
    }
}

__device__ __forceinline__ void mma_frags(float acc[4][4][4], const Frag& f)
{
    // ldmatrix.x4 matrix order (our addressing):
    //   reg0 = n0-7|k0-7, reg1 = n8-15|k0-7, reg2 = n0-7|k8-15, reg3 = n8-15|k8-15
    // mma B fragment wants {k-lo, k-hi} of ONE n-block:
    //   n-block even -> (reg0, reg2); n-block odd -> (reg1, reg3)
    #pragma unroll
    for (int mi = 0; mi < 4; mi++)
        #pragma unroll
        for (int ni = 0; ni < 4; ni++) {
            const int nb = ni >> 1, sel = ni & 1;
            float* d = acc[mi][ni];
            mma16816(d[0], d[1], d[2], d[3],
                     f.ah[mi][0], f.ah[mi][1], f.ah[mi][2], f.ah[mi][3],
                     f.bh[nb][sel], f.bh[nb][sel + 2]);
            mma16816(d[0], d[1], d[2], d[3],
                     f.ah[mi][0], f.ah[mi][1], f.ah[mi][2], f.ah[mi][3],
                     f.bl[nb][sel], f.bl[nb][sel + 2]);
            mma16816(d[0], d[1], d[2], d[3],
                     f.al[mi][0], f.al[mi][1], f.al[mi][2], f.al[mi][3],
                     f.bh[nb][sel], f.bh[nb][sel + 2]);
        }
}

// ---------------- GEMM1: scores^T = 3-term-split dec * enc^T ----------------
// C[t][e] = sum_d dec[t,d] * enc[e,d]; fused per-column softmax partials.
__global__ __launch_bounds__(256, 1)
void gemm1_scores()
{
    const int M = TT, N = EE, K = DDIM;

    extern __shared__ char dsm[];
    const uint32_t db = (smem_u32(dsm) + 1023u) & ~1023u;

    const int tid  = threadIdx.x;
    const int wid  = tid >> 5;
    const int lane = tid & 31;
    const int b    = blockIdx.z;
    const int nc0  = blockIdx.x * 128;
    const int mr0  = blockIdx.y * 128;

    const int wm = wid & 1;
    const int wn = wid >> 1;
    const int wmr = wm * 64;
    const int wnr = wn * 32;

    const int sub = lane >> 3;
    const int lr  = ((sub & 1) << 3) + (lane & 7);
    const int lc  = sub >> 1;

    const __nv_bfloat16* pAh = g_decH + (size_t)b * M * K + (size_t)mr0 * K;
    const __nv_bfloat16* pAl = g_decL + (size_t)b * M * K + (size_t)mr0 * K;
    const __nv_bfloat16* pBh = g_encH + (size_t)b * N * K + (size_t)nc0 * K;
    const __nv_bfloat16* pBl = g_encL + (size_t)b * N * K + (size_t)nc0 * K;

    float acc[4][4][4];
    #pragma unroll
    for (int i = 0; i < 4; i++)
        #pragma unroll
        for (int j = 0; j < 4; j++) {
            acc[i][j][0] = 0.f; acc[i][j][1] = 0.f;
            acc[i][j][2] = 0.f; acc[i][j][3] = 0.f;
        }

    const int NC = K / 64;
    load_stage(db, 0, pAh, pAl, pBh, pBl, 0, K, tid);
    load_stage(db, 1, pAh, pAl, pBh, pBl, 64, K, tid);

    Frag fr[2];
    for (int c = 0; c < NC; c++) {
        if (c + 1 < NC) cp_wait1(); else cp_wait0();
        __syncthreads();

        if (c + 2 < NC)
            load_stage(db, (c + 2) % NSTAGE, pAh, pAl, pBh, pBl, (c + 2) * 64, K, tid);

        const uint32_t sb  = db + (c % NSTAGE) * STAGE_BYTES;
        const uint32_t tAh = sb;
        const uint32_t tAl = sb + TILE_BYTES;
        const uint32_t tBh = sb + 2 * TILE_BYTES;
        const uint32_t tBl = sb + 3 * TILE_BYTES;

        load_frags(fr[0], tAh, tAl, tBh, tBl, 0, lc, lr, wmr, wnr);
        #pragma unroll
        for (int kk = 0; kk < 4; kk++) {
            if (kk < 3)
                load_frags(fr[(kk + 1) & 1], tAh, tAl, tBh, tBl, kk + 1, lc, lr, wmr, wnr);
            mma_frags(acc, fr[kk & 1]);
        }
    }

    // epilogue
    const int g  = lane >> 2;
    const int tg = lane & 3;
    float* Cb = g_scores + (size_t)b * M * N;
    #pragma unroll
    for (int mi = 0; mi < 4; mi++) {
        const int r0 = mr0 + wmr + mi * 16 + g;
        #pragma unroll
        for (int ni = 0; ni < 4; ni++) {
            const int col = nc0 + wnr + ni * 8 + 2 * tg;
            float2 v0 = make_float2(acc[mi][ni][0], acc[mi][ni][1]);
            float2 v1 = make_float2(acc[mi][ni][2], acc[mi][ni][3]);
            *(float2*)&Cb[(size_t)r0 * N + col]       = v0;
            *(float2*)&Cb[(size_t)(r0 + 8) * N + col] = v1;
        }
    }

    // fused column softmax partials over this warp's 64 rows
    {
        const int seg = blockIdx.y * 2 + wm;               // 0..31
        float* mp = g_mpart + ((size_t)b * NSEG + seg) * EE;
        float* sp = g_spart + ((size_t)b * NSEG + seg) * EE;
        #pragma unroll
        for (int ni = 0; ni < 4; ni++) {
            float m0 = -1e30f, m1 = -1e30f;
            #pragma unroll
            for (int mi = 0; mi < 4; mi++) {
                m0 = fmaxf(m0, fmaxf(acc[mi][ni][0], acc[mi][ni][2]));
                m1 = fmaxf(m1, fmaxf(acc[mi][ni][1], acc[mi][ni][3]));
            }
            #pragma unroll
            for (int o = 4; o < 32; o <<= 1) {
                m0 = fmaxf(m0, __shfl_xor_sync(0xffffffffu, m0, o));
                m1 = fmaxf(m1, __shfl_xor_sync(0xffffffffu, m1, o));
            }
            float s0 = 0.f, s1 = 0.f;
            #pragma unroll
            for (int mi = 0; mi < 4; mi++) {
                s0 += __expf(acc[mi][ni][0] - m0) + __expf(acc[mi][ni][2] - m0);
                s1 += __expf(acc[mi][ni][1] - m1) + __expf(acc[mi][ni][3] - m1);
            }
            #pragma unroll
            for (int o = 4; o < 32; o <<= 1) {
                s0 += __shfl_xor_sync(0xffffffffu, s0, o);
                s1 += __shfl_xor_sync(0xffffffffu, s1, o);
            }
            if (lane < 4) {   // g==0 lanes; tg == lane
                const int e = nc0 + wnr + ni * 8 + 2 * lane;
                mp[e] = m0; mp[e + 1] = m1;
                sp[e] = s0; sp[e + 1] = s1;
            }
        }
    }
}

// ---------------- GEMM2: out = P^T(fp16) * encT(fp16)^T, single term --------
// out[t][d] = sum_e Pt[t,e] * encT[d,e]
__device__ __forceinline__ void g2_load_stage(uint32_t db, int stage,
    const __half* pA, const __half* pB, int k0, int K, int tid)
{
    const __half* srcs[2] = { pA + k0, pB + k0 };
    uint32_t sbase = db + stage * G2_STAGE_BYTES;
    #pragma unroll
    for (int tt = 0; tt < 2; tt++) {
        const __half* s = srcs[tt];
        uint32_t tb = sbase + tt * TILE_BYTES;
        #pragma unroll
        for (int ii = 0; ii < 4; ii++) {
            int i = tid + ii * 256;
            int r = i >> 3, c = i & 7;
            cp_async16(tb + SW128(r * 128 + c * 16), s + (size_t)r * K + c * 8);
        }
    }
    cp_commit();
}

__global__ __launch_bounds__(256, 2)
void gemm2_fp16(float* __restrict__ outPtr)
{
    const int M = TT, N = DDIM, K = EE;

    extern __shared__ char dsm[];
    const uint32_t db = (smem_u32(dsm) + 1023u) & ~1023u;

    const int tid  = threadIdx.x;
    const int wid  = tid >> 5;
    const int lane = tid & 31;
    const int b    = blockIdx.z;
    const int nc0  = blockIdx.x * 128;
    const int mr0  = blockIdx.y * 128;

    const int wm = wid & 1;
    const int wn = wid >> 1;
    const int wmr = wm * 64;
    const int wnr = wn * 32;

    const int sub = lane >> 3;
    const int lr  = ((sub & 1) << 3) + (lane & 7);
    const int lc  = sub >> 1;

    const __half* pA = g_ptF   + (size_t)b * M * K + (size_t)mr0 * K;
    const __half* pB = g_encTF + (size_t)b * N * K + (size_t)nc0 * K;

    float acc[4][4][4];
    #pragma unroll
    for (int i = 0; i < 4; i++)
        #pragma unroll
        for (int j = 0; j < 4; j++) {
            acc[i][j][0] = 0.f; acc[i][j][1] = 0.f;
            acc[i][j][2] = 0.f; acc[i][j][3] = 0.f;
        }

    const int NC = K / 64;   // 32
    g2_load_stage(db, 0, pA, pB, 0, K, tid);
    g2_load_stage(db, 1, pA, pB, 64, K, tid);

    for (int c = 0; c < NC; c++) {
        if (c + 1 < NC) cp_wait1(); else cp_wait0();
        __syncthreads();

        if (c + 2 < NC)
            g2_load_stage(db, (c + 2) % NSTAGE, pA, pB, (c + 2) * 64, K, tid);

        const uint32_t sb = db + (c % NSTAGE) * G2_STAGE_BYTES;
        const uint32_t tA = sb;
        const uint32_t tB = sb + TILE_BYTES;

        #pragma unroll
        for (int kk = 0; kk < 4; kk++) {
            const int c16 = (2 * kk + lc) * 16;
            uint32_t a[4][4], bfr[2][4];
            #pragma unroll
            for (int mi = 0; mi < 4; mi++) {
                const uint32_t off = SW128((uint32_t)(wmr + mi * 16 + lr) * 128 + c16);
                ldsm_x4(a[mi][0], a[mi][1], a[mi][2], a[mi][3], tA + off);
            }
            #pragma unroll
            for (int nb = 0; nb < 2; nb++) {
                const uint32_t off = SW128((uint32_t)(wnr + nb * 16 + lr) * 128 + c16);
                ldsm_x4(bfr[nb][0], bfr[nb][1], bfr[nb][2], bfr[nb][3], tB + off);
            }
            #pragma unroll
            for (int mi = 0; mi < 4; mi++)
                #pragma unroll
                for (int ni = 0; ni < 4; ni++) {
                    const int nb = ni >> 1, sel = ni & 1;
                    float* d = acc[mi][ni];
                    mma16816h(d[0], d[1], d[2], d[3],
                              a[mi][0], a[mi][1], a[mi][2], a[mi][3],
                              bfr[nb][sel], bfr[nb][sel + 2]);
                }
        }
    }

    const int g  = lane >> 2;
    const int tg = lane & 3;
    float* Cb = outPtr + (size_t)b * M * N;
    #pragma unroll
    for (int mi = 0; mi < 4; mi++) {
        const int r0 = mr0 + wmr + mi * 16 + g;
        #pragma unroll
        for (int ni = 0; ni < 4; ni++) {
            const int col = nc0 + wnr + ni * 8 + 2 * tg;
            float2 v0 = make_float2(acc[mi][ni][0], acc[mi][ni][1]);
            float2 v1 = make_float2(acc[mi][ni][2], acc[mi][ni][3]);
            *(float2*)&Cb[(size_t)r0 * N + col]       = v0;
            *(float2*)&Cb[(size_t)(r0 + 8) * N + col] = v1;
        }
    }
}

// ---------------- split fp32 -> (hi, lo) bf16 -------------------------------
__device__ __forceinline__ void split1(float x, __nv_bfloat16& h, __nv_bfloat16& l) {
    h = __float2bfloat16(x);
    l = __float2bfloat16(x - __bfloat162float(h));
}

// dec: row-major split only
__global__ __launch_bounds__(256)
void split_dec(const float* __restrict__ dec)
{
    size_t j = (size_t)blockIdx.x * blockDim.x + threadIdx.x;   // over 4.19M float4
    float4 v = ((const float4*)dec)[j];
    __nv_bfloat16 h0, h1, h2, h3, l0, l1, l2, l3;
    split1(v.x, h0, l0); split1(v.y, h1, l1); split1(v.z, h2, l2); split1(v.w, h3, l3);
    *(__nv_bfloat162*)&g_decH[j * 4]     = make_bfloat162(h0, h1);
    *(__nv_bfloat162*)&g_decH[j * 4 + 2] = make_bfloat162(h2, h3);
    *(__nv_bfloat162*)&g_decL[j * 4]     = make_bfloat162(l0, l1);
    *(__nv_bfloat162*)&g_decL[j * 4 + 2] = make_bfloat162(l2, l3);
}

// enc: single read -> bf16 split (encH/encL) + transposed fp16 (encTF)
__global__ __launch_bounds__(256)
void split_enc_fused(const float* __restrict__ enc)
{
    __shared__ float ts[32][33];
    const int b = blockIdx.z;
    const int d0 = blockIdx.x * 32;
    const int e0 = blockIdx.y * 32;
    const int tx = threadIdx.x, ty = threadIdx.y;   // (32, 8)
    const float* src = enc + (size_t)b * EE * DDIM;
    __nv_bfloat16* rh = g_encH + (size_t)b * EE * DDIM;
    __nv_bfloat16* rl = g_encL + (size_t)b * EE * DDIM;
    #pragma unroll
    for (int j = 0; j < 4; j++) {
        const size_t o = (size_t)(e0 + ty + 8 * j) * DDIM + d0 + tx;
        float v = src[o];
        ts[ty + 8 * j][tx] = v;
        __nv_bfloat16 h, l; split1(v, h, l);
        rh[o] = h; rl[o] = l;
    }
    __syncthreads();
    __half* of = g_encTF + (size_t)b * DDIM * EE;
    #pragma unroll
    for (int j = 0; j < 4; j++) {
        float v = ts[tx][ty + 8 * j];
        size_t o = (size_t)(d0 + ty + 8 * j) * EE + e0 + tx;
        of[o] = __float2half_rn(v);
    }
}

// ---------------- combine 32 segments -> column max & inv-sum ---------------
__global__ __launch_bounds__(256)
void colstats_comb()
{
    const int i = blockIdx.x * 256 + threadIdx.x;   // over BB*EE
    const int b = i / EE, e = i % EE;
    float M = -1e30f;
    #pragma unroll
    for (int s = 0; s < NSEG; s++)
        M = fmaxf(M, g_mpart[((size_t)b * NSEG + s) * EE + e]);
    float S = 0.f;
    #pragma unroll
    for (int s = 0; s < NSEG; s++) {
        size_t idx = ((size_t)b * NSEG + s) * EE + e;
        S += g_spart[idx] * __expf(g_mpart[idx] - M);
    }
    g_colM[i] = M;
    g_colIS[i] = 1.0f / S;
}

// ---------------- normalize: scores -> ptF (fp16) ---------------------------
__global__ __launch_bounds__(256)
void softmax_split()
{
    size_t i = ((size_t)blockIdx.x * blockDim.x + threadIdx.x) * 4;  // [b][t][e]
    const int e = (int)(i % EE);
    const int b = (int)(i / ((size_t)TT * EE));
    float4 v = *(const float4*)&g_scores[i];
    float4 m4 = *(const float4*)&g_colM[b * EE + e];
    float4 s4 = *(const float4*)&g_colIS[b * EE + e];
    float p0 = __expf(v.x - m4.x) * s4.x;
    float p1 = __expf(v.y - m4.y) * s4.y;
    float p2 = __expf(v.z - m4.z) * s4.z;
    float p3 = __expf(v.w - m4.w) * s4.w;
    *(__half2*)&g_ptF[i]     = __floats2half2_rn(p0, p1);
    *(__half2*)&g_ptF[i + 2] = __floats2half2_rn(p2, p3);
}

// ---------------------------------------------------------------------------
extern "C" void kernel_launch(void* const* d_in, const int* in_sizes, int n_in,
                              void* d_out, int out_size)
{
    const float* enc = (const float*)d_in[0];
    const float* dec = (const float*)d_in[1];
    float* out = (float*)d_out;

    cudaFuncSetAttribute(gemm1_scores, cudaFuncAttributeMaxDynamicSharedMemorySize,
                         GEMM_SMEM);
    cudaFuncSetAttribute(gemm2_fp16, cudaFuncAttributeMaxDynamicSharedMemorySize,
                         G2_SMEM);

    {
        dim3 g(DDIM / 32, EE / 32, BB);
        split_enc_fused<<<g, dim3(32, 8)>>>(enc);
    }
    split_dec<<<16384, 256>>>(dec);
    {
        dim3 g(EE / 128, TT / 128, BB);
        gemm1_scores<<<g, 256, GEMM_SMEM>>>();
    }
    colstats_comb<<<BB * EE / 256, 256>>>();
    softmax_split<<<32768, 256>>>();
    {
        dim3 g(DDIM / 128, TT / 128, BB);
        gemm2_fp16<<<g, 256, G2_SMEM>>>(out);
    }
}